// round 16
// baseline (speedup 1.0000x reference)
#include <cuda_runtime.h>
#include <cstdint>

#define BB   4
#define CCH  64
#define HH   180
#define WWD  320
#define HWP  (HH*WWD)
#define NELT ((size_t)BB*HWP*CCH)

__device__ __forceinline__ uint32_t pack_bf2(float lo, float hi){
    uint32_t u; asm("cvt.rn.bf16x2.f32 %0, %1, %2;" : "=r"(u) : "f"(hi), "f"(lo)); return u;
}
__device__ __forceinline__ uint32_t sptr(const void* p){
    return (uint32_t)__cvta_generic_to_shared(p);
}
__device__ __forceinline__ float fex2(float x){
    float y; asm("ex2.approx.f32 %0, %1;" : "=f"(y) : "f"(x)); return y;
}
__device__ __forceinline__ void mma_bf16(float d[4], const uint32_t a[4], const uint32_t b[2]){
    asm volatile("mma.sync.aligned.m16n8k16.row.col.f32.bf16.bf16.f32 "
                 "{%0,%1,%2,%3}, {%4,%5,%6,%7}, {%8,%9}, {%0,%1,%2,%3};"
                 : "+f"(d[0]), "+f"(d[1]), "+f"(d[2]), "+f"(d[3])
                 : "r"(a[0]), "r"(a[1]), "r"(a[2]), "r"(a[3]), "r"(b[0]), "r"(b[1]));
}
__device__ __forceinline__ void ldsm4(uint32_t r[4], uint32_t a){
    asm volatile("ldmatrix.sync.aligned.m8n8.x4.shared.b16 {%0,%1,%2,%3}, [%4];"
        : "=r"(r[0]), "=r"(r[1]), "=r"(r[2]), "=r"(r[3]) : "r"(a));
}
__device__ __forceinline__ void ldsm4t(uint32_t r[4], uint32_t a){
    asm volatile("ldmatrix.sync.aligned.m8n8.x4.trans.shared.b16 {%0,%1,%2,%3}, [%4];"
        : "=r"(r[0]), "=r"(r[1]), "=r"(r[2]), "=r"(r[3]) : "r"(a));
}
__device__ __forceinline__ void ldsm2t(uint32_t r[2], uint32_t a){
    asm volatile("ldmatrix.sync.aligned.m8n8.x2.trans.shared.b16 {%0,%1}, [%2];"
        : "=r"(r[0]), "=r"(r[1]) : "r"(a));
}

// smem layout (words)
#define SM_CS   0                    // cs[320]
#define SM_RS   320                  // rs[2][64]
#define SM_W    448                  // weight buf [64][36]
#define SM_QL   2752                 // Ql [64][164]
#define SM_QR   13248                // Qr [64][164]
#define SM_VL   23744                // Vl [64][164]
#define SM_VR   34240                // Vr [64][164]
#define SM_X    44736                // xbf [320][36]  (aliased with E [64][164])
#define SM_TOTW 56256                // 225024 bytes

// GEMM1 mainloop: C1[2][5][4] = Ql_strip^T @ Qr (bf16, both [c][w], ldsm-trans)
__device__ __forceinline__ void gemm1_compute(
    uint32_t aB, uint32_t bB, uint32_t b2B, float C1[2][5][4])
{
    #pragma unroll
    for (int mt = 0; mt < 2; mt++)
        #pragma unroll
        for (int nt = 0; nt < 5; nt++)
            #pragma unroll
            for (int k = 0; k < 4; k++) C1[mt][nt][k] = 0.f;
    #pragma unroll
    for (int ks = 0; ks < 4; ks++) {
        uint32_t ra[4], rb[4], bb0[4], bb1[4], bb2[2];
        ldsm4t(ra, aB + ks*10496);
        ldsm4t(rb, aB + 32 + ks*10496);
        uint32_t a0[4] = {ra[0], ra[2], ra[1], ra[3]};
        uint32_t a1[4] = {rb[0], rb[2], rb[1], rb[3]};
        ldsm4t(bb0, bB + ks*10496);
        ldsm4t(bb1, bB + 32 + ks*10496);
        ldsm2t(bb2, b2B + ks*10496);
        mma_bf16(C1[0][0], a0, bb0);   mma_bf16(C1[0][1], a0, bb0 + 2);
        mma_bf16(C1[0][2], a0, bb1);   mma_bf16(C1[0][3], a0, bb1 + 2);
        mma_bf16(C1[0][4], a0, bb2);
        mma_bf16(C1[1][0], a1, bb0);   mma_bf16(C1[1][1], a1, bb0 + 2);
        mma_bf16(C1[1][2], a1, bb1);   mma_bf16(C1[1][3], a1, bb1 + 2);
        mma_bf16(C1[1][4], a1, bb2);
    }
}

// proj GEMM: Out[o 64][p 320] (bf16, stride 164w) = (W[o][c] @ Xb[p][c]^T + bias) * scl
__device__ __forceinline__ void proj_gemm(
    const uint32_t* Wb, const uint32_t* Xb, uint32_t* Out, const float* bias,
    float scl, int wid, int g, int t, int grp, int r8)
{
    int wyP = wid >> 2, wxP = wid & 3;
    int m0 = wyP * 16;
    float C[10][4];
    #pragma unroll
    for (int nt = 0; nt < 10; nt++)
        #pragma unroll
        for (int k = 0; k < 4; k++) C[nt][k] = 0.f;

    uint32_t aB = sptr(Wb) + (uint32_t)((m0 + r8 + 8*(grp&1))*144 + 16*(grp>>1));
    uint32_t bB = sptr(Xb) + (uint32_t)((wxP*80 + r8 + 8*(grp>>1))*144 + 16*(grp&1));
    #pragma unroll
    for (int ks = 0; ks < 4; ks++) {
        uint32_t a[4];
        ldsm4(a, aB + ks*32);
        #pragma unroll
        for (int j = 0; j < 5; j++) {
            uint32_t bv4[4];
            ldsm4(bv4, bB + j*2304 + ks*32);
            mma_bf16(C[2*j],   a, bv4);
            mma_bf16(C[2*j+1], a, bv4 + 2);
        }
    }
    float b0 = bias[m0 + g], b1 = bias[m0 + g + 8];
    #pragma unroll
    for (int nt = 0; nt < 10; nt++) {
        int w = wxP*40 + nt*4 + t;
        Out[(m0 + g)*164 + w]     = pack_bf2((C[nt][0] + b0)*scl, (C[nt][1] + b0)*scl);
        Out[(m0 + g + 8)*164 + w] = pack_bf2((C[nt][2] + b1)*scl, (C[nt][3] + b1)*scl);
    }
}

__global__ __launch_bounds__(512, 1) void sfam_fused_kernel(
    const float* __restrict__ x_l, const float* __restrict__ x_r,
    const float* __restrict__ lnw_l, const float* __restrict__ lnb_l,
    const float* __restrict__ lnw_r, const float* __restrict__ lnb_r,
    const float* __restrict__ wq_l,  const float* __restrict__ bq_l,
    const float* __restrict__ wq_r,  const float* __restrict__ bq_r,
    const float* __restrict__ wv_l,  const float* __restrict__ bv_l,
    const float* __restrict__ wv_r,  const float* __restrict__ bv_r,
    const float* __restrict__ beta,  const float* __restrict__ gamma,
    float* __restrict__ out_l, float* __restrict__ out_r)
{
    extern __shared__ float sm[];
    float*    cs  = sm + SM_CS;
    float*    rsA = sm + SM_RS;
    uint32_t* Wb  = (uint32_t*)(sm + SM_W);
    uint32_t* Qlw = (uint32_t*)(sm + SM_QL);
    uint32_t* Qrw = (uint32_t*)(sm + SM_QR);
    uint32_t* Vlw = (uint32_t*)(sm + SM_VL);
    uint32_t* Vrw = (uint32_t*)(sm + SM_VR);
    uint32_t* Xb  = (uint32_t*)(sm + SM_X);
    uint32_t* Ew  = (uint32_t*)(sm + SM_X);   // alias: E after proj phase

    int tid = threadIdx.x, lane = tid & 31, wid = tid >> 5;
    int g = lane >> 2, t = lane & 3;
    int grp = lane >> 3, r8 = lane & 7;
    int bh = blockIdx.x, b = bh / HH, h = bh - b * HH;
    size_t cmb = (size_t)b * CCH * HWP + h * WWD;

    if (tid < 320) cs[tid] = 0.f;
    if (tid >= 320 && tid < 448) rsA[tid - 320] = 0.f;

    // ---------------- projection phase (both sides) ----------------
    #pragma unroll 1
    for (int side = 0; side < 2; side++) {
        const float* xrow = (side ? x_r : x_l) + cmb;
        const float* lnw  = side ? lnw_r : lnw_l;
        const float* lnb  = side ? lnb_r : lnb_l;
        const float* wq   = side ? wq_r  : wq_l;
        const float* bq   = side ? bq_r  : bq_l;
        const float* wv   = side ? wv_r  : wv_l;
        const float* bv   = side ? bv_r  : bv_l;
        uint32_t* Qbuf = side ? Qrw : Qlw;
        uint32_t* Vbuf = side ? Vrw : Vlw;
        // Ql gets 0.125 (attn scale) * log2(e) folded in: exp(x*0.125) = ex2(x*0.18034)
        float qscale = side ? 1.0f : 0.18033688f;

        float mu = 0.f, rsig = 0.f;
        if (tid < 320) {   // stage x (bf16) + LN stats (fp32)
            float s_ = 0.f, ss_ = 0.f;
            #pragma unroll 8
            for (int ci = 0; ci < 32; ci++) {
                float v0 = xrow[(size_t)(2*ci) * HWP + tid];
                float v1 = xrow[(size_t)(2*ci + 1) * HWP + tid];
                s_ += v0 + v1; ss_ += v0*v0 + v1*v1;
                Xb[tid*36 + ci] = pack_bf2(v0, v1);
            }
            float m = s_ * 0.015625f;
            mu = m;
            rsig = rsqrtf(ss_ * 0.015625f - m*m + 1e-6f);
        }
        {   // stage wv -> bf16 [o][c]
            const float2* wsrc = (const float2*)wv;
            #pragma unroll
            for (int i = 0; i < 4; i++) {
                int j = i * 512 + tid;
                float2 w2 = wsrc[j];
                Wb[(j >> 5)*36 + (j & 31)] = pack_bf2(w2.x, w2.y);
            }
        }
        __syncthreads();
        proj_gemm(Wb, Xb, Vbuf, bv, 1.0f, wid, g, t, grp, r8);   // V = wv @ x
        __syncthreads();
        if (tid < 320) {   // normalize x in place
            #pragma unroll 8
            for (int w = 0; w < 32; w++) {
                uint32_t u = Xb[tid*36 + w];
                float lo = __uint_as_float(u << 16);
                float hi = __uint_as_float(u & 0xffff0000u);
                float y0 = (lo - mu) * rsig * lnw[2*w]     + lnb[2*w];
                float y1 = (hi - mu) * rsig * lnw[2*w + 1] + lnb[2*w + 1];
                Xb[tid*36 + w] = pack_bf2(y0, y1);
            }
        }
        {   // stage wq
            const float2* wsrc = (const float2*)wq;
            #pragma unroll
            for (int i = 0; i < 4; i++) {
                int j = i * 512 + tid;
                float2 w2 = wsrc[j];
                Wb[(j >> 5)*36 + (j & 31)] = pack_bf2(w2.x, w2.y);
            }
        }
        __syncthreads();
        proj_gemm(Wb, Xb, Qbuf, bq, qscale, wid, g, t, grp, r8); // Q = wq @ LN(x)
        __syncthreads();
    }

    // ---------------- flash attention phase (pipelined GEMM1) ----------------
    int wy3 = wid & 1, wx3 = wid >> 1;
    float C3[2][5][4];
    #pragma unroll
    for (int mt = 0; mt < 2; mt++)
        #pragma unroll
        for (int nt = 0; nt < 5; nt++)
            #pragma unroll
            for (int k = 0; k < 4; k++) C3[mt][nt][k] = 0.f;

    // GEMM1 per-warp constants
    int wy1 = wid >> 3, wx1 = wid & 7;
    int n0g1 = wx1 * 40;
    uint32_t g1_aBase = sptr(Qlw) + (uint32_t)((r8 + 8*(grp&1))*656 + (wy1*32 + 8*(grp>>1))*2);
    uint32_t g1_bB    = sptr(Qrw) + (uint32_t)((r8 + 8*(grp&1))*656 + (n0g1 + 8*(grp>>1))*2);
    uint32_t g1_b2B   = sptr(Qrw) + (uint32_t)((r8 + 8*(grp&1))*656 + (n0g1 + 32)*2);

    float C1[2][5][4];
    gemm1_compute(g1_aBase, g1_bB, g1_b2B, C1);   // strip 0

    #pragma unroll 1
    for (int s = 0; s < 5; s++) {
        int wl0 = s * 64;
        float* rs = rsA + (s & 1) * 64;

        __syncthreads();   // (X) prior-strip E readers done; E writable

        // ---- GEMM1 epilogue: E = ex2(C1), row sums, col sums ----
        {
            int m0 = wy1 * 32;
            float rsum[2][2];
            rsum[0][0]=rsum[0][1]=rsum[1][0]=rsum[1][1]=0.f;
            #pragma unroll
            for (int nt = 0; nt < 5; nt++) {
                float cv0 = 0.f, cv1 = 0.f;
                #pragma unroll
                for (int mt = 0; mt < 2; mt++) {
                    float e0 = fex2(C1[mt][nt][0]);
                    float e1 = fex2(C1[mt][nt][1]);
                    float e2 = fex2(C1[mt][nt][2]);
                    float e3 = fex2(C1[mt][nt][3]);
                    int row = m0 + mt*16 + g;
                    int cw  = wx1*20 + nt*4 + t;
                    Ew[row * 164 + cw]       = pack_bf2(e0, e1);
                    Ew[(row + 8) * 164 + cw] = pack_bf2(e2, e3);
                    rsum[mt][0] += e0 + e1;
                    rsum[mt][1] += e2 + e3;
                    cv0 += e0 + e2;
                    cv1 += e1 + e3;
                }
                cv0 += __shfl_xor_sync(~0u, cv0, 4);
                cv0 += __shfl_xor_sync(~0u, cv0, 8);
                cv0 += __shfl_xor_sync(~0u, cv0, 16);
                cv1 += __shfl_xor_sync(~0u, cv1, 4);
                cv1 += __shfl_xor_sync(~0u, cv1, 8);
                cv1 += __shfl_xor_sync(~0u, cv1, 16);
                if (g == 0) {
                    int col = n0g1 + nt*8 + 2*t;
                    atomicAdd(&cs[col], cv0);
                    atomicAdd(&cs[col + 1], cv1);
                }
            }
            #pragma unroll
            for (int mt = 0; mt < 2; mt++) {
                float s0 = rsum[mt][0], s1 = rsum[mt][1];
                s0 += __shfl_xor_sync(~0u, s0, 1); s0 += __shfl_xor_sync(~0u, s0, 2);
                s1 += __shfl_xor_sync(~0u, s1, 1); s1 += __shfl_xor_sync(~0u, s1, 2);
                if (t == 0) {
                    atomicAdd(&rs[m0 + mt*16 + g], s0);
                    atomicAdd(&rs[m0 + mt*16 + g + 8], s1);
                }
            }
        }
        __syncthreads();   // (Y) E + rs ready

        if (s < 4 && tid < 64) rsA[((s + 1) & 1)*64 + tid] = 0.f;

        // ---- GEMM2': F^T[c][wl] = Vr @ E^T, K=320, x_l prefetched ----
        {
            int wy2 = wid >> 2, wx2 = wid & 3;
            int m0 = wy2 * 16, n0 = wx2 * 16;
            uint32_t aBase = sptr(Vrw) + (uint32_t)((m0 + r8 + 8*(grp&1))*656 + 16*(grp>>1));
            uint32_t bBase = sptr(Ew)  + (uint32_t)((n0 + r8 + 8*(grp>>1))*656 + 16*(grp&1));
            const float* xl = x_l + cmb;
            int c0 = m0 + g;
            int wla = n0 + 2*t, wlb = n0 + 8 + 2*t;
            float2 x0a = *(const float2*)(xl + (size_t)c0*HWP + wl0 + wla);
            float2 x1a = *(const float2*)(xl + (size_t)(c0+8)*HWP + wl0 + wla);
            float2 x0b = *(const float2*)(xl + (size_t)c0*HWP + wl0 + wlb);
            float2 x1b = *(const float2*)(xl + (size_t)(c0+8)*HWP + wl0 + wlb);

            float C2[2][4];
            #pragma unroll
            for (int nt = 0; nt < 2; nt++)
                #pragma unroll
                for (int k = 0; k < 4; k++) C2[nt][k] = 0.f;
            #pragma unroll 5
            for (int ks = 0; ks < 20; ks++) {
                uint32_t a[4], bbv[4];
                ldsm4(a, aBase + ks*32);
                ldsm4(bbv, bBase + ks*32);
                mma_bf16(C2[0], a, bbv);
                mma_bf16(C2[1], a, bbv + 2);
            }
            float* ol = out_l + cmb;
            float bt0 = beta[c0], bt1 = beta[c0 + 8];
            {
                float ri0 = __fdividef(1.f, rs[wla]);
                float ri1 = __fdividef(1.f, rs[wla + 1]);
                *(float2*)(ol + (size_t)c0*HWP + wl0 + wla) = make_float2(
                    x0a.x + bt0*ri0*C2[0][0], x0a.y + bt0*ri1*C2[0][1]);
                *(float2*)(ol + (size_t)(c0+8)*HWP + wl0 + wla) = make_float2(
                    x1a.x + bt1*ri0*C2[0][2], x1a.y + bt1*ri1*C2[0][3]);
            }
            {
                float ri0 = __fdividef(1.f, rs[wlb]);
                float ri1 = __fdividef(1.f, rs[wlb + 1]);
                *(float2*)(ol + (size_t)c0*HWP + wl0 + wlb) = make_float2(
                    x0b.x + bt0*ri0*C2[1][0], x0b.y + bt0*ri1*C2[1][1]);
                *(float2*)(ol + (size_t)(c0+8)*HWP + wl0 + wlb) = make_float2(
                    x1b.x + bt1*ri0*C2[1][2], x1b.y + bt1*ri1*C2[1][3]);
            }
        }

        // ---- GEMM3: C3 += Vl[:, strip] @ E ----
        {
            int m0 = wy3 * 32, n0 = wx3 * 40;
            uint32_t aBase  = sptr(Vlw) + (uint32_t)((m0 + r8 + 8*(grp&1))*656 + wl0*2 + 16*(grp>>1));
            uint32_t bBase  = sptr(Ew) + (uint32_t)((r8 + 8*(grp&1))*656 + (n0 + 8*(grp>>1))*2);
            uint32_t b2Base = sptr(Ew) + (uint32_t)((r8 + 8*(grp&1))*656 + (n0 + 32)*2);
            #pragma unroll
            for (int ks = 0; ks < 4; ks++) {
                uint32_t a0[4], a1[4], bb0[4], bb1[4], bb2[2];
                ldsm4(a0, aBase + ks*32);
                ldsm4(a1, aBase + 16*656 + ks*32);
                ldsm4t(bb0, bBase + ks*10496);
                ldsm4t(bb1, bBase + 32 + ks*10496);
                ldsm2t(bb2, b2Base + ks*10496);
                mma_bf16(C3[0][0], a0, bb0);   mma_bf16(C3[0][1], a0, bb0 + 2);
                mma_bf16(C3[0][2], a0, bb1);   mma_bf16(C3[0][3], a0, bb1 + 2);
                mma_bf16(C3[0][4], a0, bb2);
                mma_bf16(C3[1][0], a1, bb0);   mma_bf16(C3[1][1], a1, bb0 + 2);
                mma_bf16(C3[1][2], a1, bb1);   mma_bf16(C3[1][3], a1, bb1 + 2);
                mma_bf16(C3[1][4], a1, bb2);
            }
        }

        // ---- pipelined GEMM1 mma for next strip (reads Ql/Qr only) ----
        if (s < 4)
            gemm1_compute(g1_aBase + (uint32_t)((s + 1) * 64 * 2), g1_bB, g1_b2B, C1);
    }

    __syncthreads();
    if (tid < 320) cs[tid] = __fdividef(1.f, cs[tid]);
    __syncthreads();

    {   // out_r = x_r + gamma * (C3 * cinv)
        const float* xr = x_r + cmb;
        float* orr = out_r + cmb;
        int m0 = wy3 * 32, n0 = wx3 * 40;
        #pragma unroll
        for (int mt = 0; mt < 2; mt++) {
            int c0 = m0 + mt*16 + g;
            float g0 = gamma[c0], g1 = gamma[c0 + 8];
            #pragma unroll
            for (int nt = 0; nt < 5; nt++) {
                int col = n0 + nt*8 + 2*t;
                float ci0 = cs[col], ci1 = cs[col + 1];
                float2 x0 = *(const float2*)(xr + (size_t)c0*HWP + col);
                *(float2*)(orr + (size_t)c0*HWP + col) = make_float2(
                    x0.x + g0*ci0*C3[mt][nt][0], x0.y + g0*ci1*C3[mt][nt][1]);
                float2 x1 = *(const float2*)(xr + (size_t)(c0+8)*HWP + col);
                *(float2*)(orr + (size_t)(c0+8)*HWP + col) = make_float2(
                    x1.x + g1*ci0*C3[mt][nt][2], x1.y + g1*ci1*C3[mt][nt][3]);
            }
        }
    }
}

extern "C" void kernel_launch(void* const* d_in, const int* in_sizes, int n_in,
                              void* d_out, int out_size)
{
    const float* x_l    = (const float*)d_in[0];
    const float* x_r    = (const float*)d_in[1];
    const float* ln_l_w = (const float*)d_in[2];
    const float* ln_l_b = (const float*)d_in[3];
    const float* ln_r_w = (const float*)d_in[4];
    const float* ln_r_b = (const float*)d_in[5];
    const float* wq_l   = (const float*)d_in[6];
    const float* bq_l   = (const float*)d_in[7];
    const float* wq_r   = (const float*)d_in[8];
    const float* bq_r   = (const float*)d_in[9];
    const float* wv_l   = (const float*)d_in[10];
    const float* bv_l   = (const float*)d_in[11];
    const float* wv_r   = (const float*)d_in[12];
    const float* bv_r   = (const float*)d_in[13];
    const float* beta   = (const float*)d_in[14];
    const float* gamma  = (const float*)d_in[15];

    float* out_l = (float*)d_out;
    float* out_r = out_l + NELT;

    cudaFuncSetAttribute(sfam_fused_kernel,
                         cudaFuncAttributeMaxDynamicSharedMemorySize, SM_TOTW*4);

    sfam_fused_kernel<<<BB*HH, 512, SM_TOTW*4>>>(
        x_l, x_r, ln_l_w, ln_l_b, ln_r_w, ln_r_b,
        wq_l, bq_l, wq_r, bq_r, wv_l, bv_l, wv_r, bv_r,
        beta, gamma, out_l, out_r);
}

// round 17
// speedup vs baseline: 1.0514x; 1.0514x over previous
#include <cuda_runtime.h>
#include <cstdint>

#define BB   4
#define CCH  64
#define HH   180
#define WWD  320
#define HWP  (HH*WWD)
#define NELT ((size_t)BB*HWP*CCH)

__device__ __forceinline__ uint32_t pack_bf2(float lo, float hi){
    uint32_t u; asm("cvt.rn.bf16x2.f32 %0, %1, %2;" : "=r"(u) : "f"(hi), "f"(lo)); return u;
}
__device__ __forceinline__ uint32_t sptr(const void* p){
    return (uint32_t)__cvta_generic_to_shared(p);
}
__device__ __forceinline__ float fex2(float x){
    float y; asm("ex2.approx.f32 %0, %1;" : "=f"(y) : "f"(x)); return y;
}
__device__ __forceinline__ void mma_bf16(float d[4], const uint32_t a[4], const uint32_t b[2]){
    asm volatile("mma.sync.aligned.m16n8k16.row.col.f32.bf16.bf16.f32 "
                 "{%0,%1,%2,%3}, {%4,%5,%6,%7}, {%8,%9}, {%0,%1,%2,%3};"
                 : "+f"(d[0]), "+f"(d[1]), "+f"(d[2]), "+f"(d[3])
                 : "r"(a[0]), "r"(a[1]), "r"(a[2]), "r"(a[3]), "r"(b[0]), "r"(b[1]));
}
__device__ __forceinline__ void ldsm4(uint32_t r[4], uint32_t a){
    asm volatile("ldmatrix.sync.aligned.m8n8.x4.shared.b16 {%0,%1,%2,%3}, [%4];"
        : "=r"(r[0]), "=r"(r[1]), "=r"(r[2]), "=r"(r[3]) : "r"(a));
}
__device__ __forceinline__ void ldsm4t(uint32_t r[4], uint32_t a){
    asm volatile("ldmatrix.sync.aligned.m8n8.x4.trans.shared.b16 {%0,%1,%2,%3}, [%4];"
        : "=r"(r[0]), "=r"(r[1]), "=r"(r[2]), "=r"(r[3]) : "r"(a));
}
__device__ __forceinline__ void ldsm2t(uint32_t r[2], uint32_t a){
    asm volatile("ldmatrix.sync.aligned.m8n8.x2.trans.shared.b16 {%0,%1}, [%2];"
        : "=r"(r[0]), "=r"(r[1]) : "r"(a));
}

// smem layout (words)
#define SM_CS   0                    // cs[320]
#define SM_RS   320                  // rs[2][64]
#define SM_W    448                  // weight buf [64][36]
#define SM_QL   2752                 // Ql [64][164]
#define SM_QR   13248                // Qr [64][164]
#define SM_VL   23744                // Vl [64][164]
#define SM_VR   34240                // Vr [64][164]
#define SM_X    44736                // xbf [320][36]  (aliased with E [64][164])
#define SM_TOTW 56256                // 225024 bytes

// proj GEMM: Out[o 64][p 320] (bf16, stride 164w) = (W[o][c] @ Xb[p][c]^T + bias) * scl
__device__ __forceinline__ void proj_gemm(
    const uint32_t* Wb, const uint32_t* Xb, uint32_t* Out, const float* bias,
    float scl, int wid, int g, int t, int grp, int r8)
{
    int wyP = wid >> 2, wxP = wid & 3;
    int m0 = wyP * 16;
    float C[10][4];
    #pragma unroll
    for (int nt = 0; nt < 10; nt++)
        #pragma unroll
        for (int k = 0; k < 4; k++) C[nt][k] = 0.f;

    uint32_t aB = sptr(Wb) + (uint32_t)((m0 + r8 + 8*(grp&1))*144 + 16*(grp>>1));
    uint32_t bB = sptr(Xb) + (uint32_t)((wxP*80 + r8 + 8*(grp>>1))*144 + 16*(grp&1));
    #pragma unroll
    for (int ks = 0; ks < 4; ks++) {
        uint32_t a[4];
        ldsm4(a, aB + ks*32);
        #pragma unroll
        for (int j = 0; j < 5; j++) {
            uint32_t bv4[4];
            ldsm4(bv4, bB + j*2304 + ks*32);
            mma_bf16(C[2*j],   a, bv4);
            mma_bf16(C[2*j+1], a, bv4 + 2);
        }
    }
    float b0 = bias[m0 + g], b1 = bias[m0 + g + 8];
    #pragma unroll
    for (int nt = 0; nt < 10; nt++) {
        int w = wxP*40 + nt*4 + t;
        Out[(m0 + g)*164 + w]     = pack_bf2((C[nt][0] + b0)*scl, (C[nt][1] + b0)*scl);
        Out[(m0 + g + 8)*164 + w] = pack_bf2((C[nt][2] + b1)*scl, (C[nt][3] + b1)*scl);
    }
}

__global__ __launch_bounds__(512, 1) void sfam_fused_kernel(
    const float* __restrict__ x_l, const float* __restrict__ x_r,
    const float* __restrict__ lnw_l, const float* __restrict__ lnb_l,
    const float* __restrict__ lnw_r, const float* __restrict__ lnb_r,
    const float* __restrict__ wq_l,  const float* __restrict__ bq_l,
    const float* __restrict__ wq_r,  const float* __restrict__ bq_r,
    const float* __restrict__ wv_l,  const float* __restrict__ bv_l,
    const float* __restrict__ wv_r,  const float* __restrict__ bv_r,
    const float* __restrict__ beta,  const float* __restrict__ gamma,
    float* __restrict__ out_l, float* __restrict__ out_r)
{
    extern __shared__ float sm[];
    float*    cs  = sm + SM_CS;
    float*    rsA = sm + SM_RS;
    uint32_t* Wb  = (uint32_t*)(sm + SM_W);
    uint32_t* Qlw = (uint32_t*)(sm + SM_QL);
    uint32_t* Qrw = (uint32_t*)(sm + SM_QR);
    uint32_t* Vlw = (uint32_t*)(sm + SM_VL);
    uint32_t* Vrw = (uint32_t*)(sm + SM_VR);
    uint32_t* Xb  = (uint32_t*)(sm + SM_X);
    uint32_t* Ew  = (uint32_t*)(sm + SM_X);   // alias: E after proj phase

    int tid = threadIdx.x, lane = tid & 31, wid = tid >> 5;
    int g = lane >> 2, t = lane & 3;
    int grp = lane >> 3, r8 = lane & 7;
    int bh = blockIdx.x, b = bh / HH, h = bh - b * HH;
    size_t cmb = (size_t)b * CCH * HWP + h * WWD;

    if (tid < 320) cs[tid] = 0.f;
    if (tid >= 320 && tid < 448) rsA[tid - 320] = 0.f;

    // ---------------- projection phase (both sides) ----------------
    #pragma unroll 1
    for (int side = 0; side < 2; side++) {
        const float* xrow = (side ? x_r : x_l) + cmb;
        const float* lnw  = side ? lnw_r : lnw_l;
        const float* lnb  = side ? lnb_r : lnb_l;
        const float* wq   = side ? wq_r  : wq_l;
        const float* bq   = side ? bq_r  : bq_l;
        const float* wv   = side ? wv_r  : wv_l;
        const float* bv   = side ? bv_r  : bv_l;
        uint32_t* Qbuf = side ? Qrw : Qlw;
        uint32_t* Vbuf = side ? Vrw : Vlw;
        // Ql gets 0.125 (attn scale) * log2(e) folded in: exp(x*0.125) = ex2(x*0.18034)
        float qscale = side ? 1.0f : 0.18033688f;

        float mu = 0.f, rsig = 0.f;
        if (tid < 320) {   // stage x (bf16) + LN stats (fp32)
            float s_ = 0.f, ss_ = 0.f;
            #pragma unroll 8
            for (int ci = 0; ci < 32; ci++) {
                float v0 = xrow[(size_t)(2*ci) * HWP + tid];
                float v1 = xrow[(size_t)(2*ci + 1) * HWP + tid];
                s_ += v0 + v1; ss_ += v0*v0 + v1*v1;
                Xb[tid*36 + ci] = pack_bf2(v0, v1);
            }
            float m = s_ * 0.015625f;
            mu = m;
            rsig = rsqrtf(ss_ * 0.015625f - m*m + 1e-6f);
        }
        {   // stage wv -> bf16 [o][c]
            const float2* wsrc = (const float2*)wv;
            #pragma unroll
            for (int i = 0; i < 4; i++) {
                int j = i * 512 + tid;
                float2 w2 = wsrc[j];
                Wb[(j >> 5)*36 + (j & 31)] = pack_bf2(w2.x, w2.y);
            }
        }
        __syncthreads();
        proj_gemm(Wb, Xb, Vbuf, bv, 1.0f, wid, g, t, grp, r8);   // V = wv @ x
        __syncthreads();
        if (tid < 320) {   // normalize x in place
            #pragma unroll 8
            for (int w = 0; w < 32; w++) {
                uint32_t u = Xb[tid*36 + w];
                float lo = __uint_as_float(u << 16);
                float hi = __uint_as_float(u & 0xffff0000u);
                float y0 = (lo - mu) * rsig * lnw[2*w]     + lnb[2*w];
                float y1 = (hi - mu) * rsig * lnw[2*w + 1] + lnb[2*w + 1];
                Xb[tid*36 + w] = pack_bf2(y0, y1);
            }
        }
        {   // stage wq
            const float2* wsrc = (const float2*)wq;
            #pragma unroll
            for (int i = 0; i < 4; i++) {
                int j = i * 512 + tid;
                float2 w2 = wsrc[j];
                Wb[(j >> 5)*36 + (j & 31)] = pack_bf2(w2.x, w2.y);
            }
        }
        __syncthreads();
        proj_gemm(Wb, Xb, Qbuf, bq, qscale, wid, g, t, grp, r8); // Q = wq @ LN(x)
        __syncthreads();
    }

    // ---------------- flash attention phase ----------------
    int wy3 = wid & 1, wx3 = wid >> 1;
    float C3[2][5][4];
    #pragma unroll
    for (int mt = 0; mt < 2; mt++)
        #pragma unroll
        for (int nt = 0; nt < 5; nt++)
            #pragma unroll
            for (int k = 0; k < 4; k++) C3[mt][nt][k] = 0.f;

    #pragma unroll 1
    for (int s = 0; s < 5; s++) {
        int wl0 = s * 64;
        float* rs = rsA + (s & 1) * 64;

        // ---- GEMM1: E = ex2(Ql_strip^T @ Qr)  (A via ldsm4t on [c][wl]) ----
        {
            int wy1 = wid >> 3, wx1 = wid & 7;
            int m0 = wy1 * 32, n0 = wx1 * 40;
            uint32_t aB  = sptr(Qlw) + (uint32_t)((r8 + 8*(grp&1))*656 + (wl0 + m0 + 8*(grp>>1))*2);
            uint32_t bB  = sptr(Qrw) + (uint32_t)((r8 + 8*(grp&1))*656 + (n0 + 8*(grp>>1))*2);
            uint32_t b2B = sptr(Qrw) + (uint32_t)((r8 + 8*(grp&1))*656 + (n0 + 32)*2);
            float C1[2][5][4];
            #pragma unroll
            for (int mt = 0; mt < 2; mt++)
                #pragma unroll
                for (int nt = 0; nt < 5; nt++)
                    #pragma unroll
                    for (int k = 0; k < 4; k++) C1[mt][nt][k] = 0.f;
            #pragma unroll
            for (int ks = 0; ks < 4; ks++) {
                uint32_t ra[4], rb[4], bb0[4], bb1[4], bb2[2];
                ldsm4t(ra, aB + ks*10496);
                ldsm4t(rb, aB + 32 + ks*10496);
                uint32_t a0[4] = {ra[0], ra[2], ra[1], ra[3]};
                uint32_t a1[4] = {rb[0], rb[2], rb[1], rb[3]};
                ldsm4t(bb0, bB + ks*10496);
                ldsm4t(bb1, bB + 32 + ks*10496);
                ldsm2t(bb2, b2B + ks*10496);
                mma_bf16(C1[0][0], a0, bb0);   mma_bf16(C1[0][1], a0, bb0 + 2);
                mma_bf16(C1[0][2], a0, bb1);   mma_bf16(C1[0][3], a0, bb1 + 2);
                mma_bf16(C1[0][4], a0, bb2);
                mma_bf16(C1[1][0], a1, bb0);   mma_bf16(C1[1][1], a1, bb0 + 2);
                mma_bf16(C1[1][2], a1, bb1);   mma_bf16(C1[1][3], a1, bb1 + 2);
                mma_bf16(C1[1][4], a1, bb2);
            }
            float rsum[2][2];
            rsum[0][0]=rsum[0][1]=rsum[1][0]=rsum[1][1]=0.f;
            #pragma unroll
            for (int nt = 0; nt < 5; nt++) {
                float cv0 = 0.f, cv1 = 0.f;
                #pragma unroll
                for (int mt = 0; mt < 2; mt++) {
                    float e0 = fex2(C1[mt][nt][0]);
                    float e1 = fex2(C1[mt][nt][1]);
                    float e2 = fex2(C1[mt][nt][2]);
                    float e3 = fex2(C1[mt][nt][3]);
                    int row = m0 + mt*16 + g;
                    int cw  = wx1*20 + nt*4 + t;
                    Ew[row * 164 + cw]       = pack_bf2(e0, e1);
                    Ew[(row + 8) * 164 + cw] = pack_bf2(e2, e3);
                    rsum[mt][0] += e0 + e1;
                    rsum[mt][1] += e2 + e3;
                    cv0 += e0 + e2;
                    cv1 += e1 + e3;
                }
                cv0 += __shfl_xor_sync(~0u, cv0, 4);
                cv0 += __shfl_xor_sync(~0u, cv0, 8);
                cv0 += __shfl_xor_sync(~0u, cv0, 16);
                cv1 += __shfl_xor_sync(~0u, cv1, 4);
                cv1 += __shfl_xor_sync(~0u, cv1, 8);
                cv1 += __shfl_xor_sync(~0u, cv1, 16);
                if (g == 0) {
                    int col = n0 + nt*8 + 2*t;
                    atomicAdd(&cs[col], cv0);
                    atomicAdd(&cs[col + 1], cv1);
                }
            }
            #pragma unroll
            for (int mt = 0; mt < 2; mt++) {
                float s0 = rsum[mt][0], s1 = rsum[mt][1];
                s0 += __shfl_xor_sync(~0u, s0, 1); s0 += __shfl_xor_sync(~0u, s0, 2);
                s1 += __shfl_xor_sync(~0u, s1, 1); s1 += __shfl_xor_sync(~0u, s1, 2);
                if (t == 0) {
                    atomicAdd(&rs[m0 + mt*16 + g], s0);
                    atomicAdd(&rs[m0 + mt*16 + g + 8], s1);
                }
            }
        }
        __syncthreads();   // (B) E + rs ready

        if (s < 4 && tid < 64) rsA[((s + 1) & 1)*64 + tid] = 0.f;

        // ---- GEMM2': F^T[c][wl] = Vr @ E^T, K=320 split into 2 halves (4 chains) ----
        {
            int wy2 = wid >> 2, wx2 = wid & 3;
            int m0 = wy2 * 16, n0 = wx2 * 16;
            uint32_t aBase = sptr(Vrw) + (uint32_t)((m0 + r8 + 8*(grp&1))*656 + 16*(grp>>1));
            uint32_t bBase = sptr(Ew)  + (uint32_t)((n0 + r8 + 8*(grp>>1))*656 + 16*(grp&1));
            float C2a[2][4], C2b[2][4];
            #pragma unroll
            for (int nt = 0; nt < 2; nt++)
                #pragma unroll
                for (int k = 0; k < 4; k++) { C2a[nt][k] = 0.f; C2b[nt][k] = 0.f; }
            #pragma unroll
            for (int ks = 0; ks < 10; ks++) {
                uint32_t a0[4], b0v[4], a1[4], b1v[4];
                ldsm4(a0, aBase + ks*32);
                ldsm4(b0v, bBase + ks*32);
                ldsm4(a1, aBase + (ks + 10)*32);
                ldsm4(b1v, bBase + (ks + 10)*32);
                mma_bf16(C2a[0], a0, b0v);
                mma_bf16(C2b[0], a1, b1v);
                mma_bf16(C2a[1], a0, b0v + 2);
                mma_bf16(C2b[1], a1, b1v + 2);
            }
            const float* xl = x_l + cmb;
            float* ol = out_l + cmb;
            int c0 = m0 + g;
            float bt0 = beta[c0], bt1 = beta[c0 + 8];
            #pragma unroll
            for (int nt = 0; nt < 2; nt++) {
                int wl = n0 + nt*8 + 2*t;
                float ri0 = __fdividef(1.f, rs[wl]);
                float ri1 = __fdividef(1.f, rs[wl + 1]);
                float f0 = C2a[nt][0] + C2b[nt][0];
                float f1 = C2a[nt][1] + C2b[nt][1];
                float f2 = C2a[nt][2] + C2b[nt][2];
                float f3 = C2a[nt][3] + C2b[nt][3];
                float2 x0 = *(const float2*)(xl + (size_t)c0*HWP + wl0 + wl);
                *(float2*)(ol + (size_t)c0*HWP + wl0 + wl) = make_float2(
                    x0.x + bt0*ri0*f0, x0.y + bt0*ri1*f1);
                float2 x1 = *(const float2*)(xl + (size_t)(c0+8)*HWP + wl0 + wl);
                *(float2*)(ol + (size_t)(c0+8)*HWP + wl0 + wl) = make_float2(
                    x1.x + bt1*ri0*f2, x1.y + bt1*ri1*f3);
            }
        }

        // ---- GEMM3: C3 += Vl[:, strip] @ E ----
        {
            int m0 = wy3 * 32, n0 = wx3 * 40;
            uint32_t aBase  = sptr(Vlw) + (uint32_t)((m0 + r8 + 8*(grp&1))*656 + wl0*2 + 16*(grp>>1));
            uint32_t bBase  = sptr(Ew) + (uint32_t)((r8 + 8*(grp&1))*656 + (n0 + 8*(grp>>1))*2);
            uint32_t b2Base = sptr(Ew) + (uint32_t)((r8 + 8*(grp&1))*656 + (n0 + 32)*2);
            #pragma unroll
            for (int ks = 0; ks < 4; ks++) {
                uint32_t a0[4], a1[4], bb0[4], bb1[4], bb2[2];
                ldsm4(a0, aBase + ks*32);
                ldsm4(a1, aBase + 16*656 + ks*32);
                ldsm4t(bb0, bBase + ks*10496);
                ldsm4t(bb1, bBase + 32 + ks*10496);
                ldsm2t(bb2, b2Base + ks*10496);
                mma_bf16(C3[0][0], a0, bb0);   mma_bf16(C3[0][1], a0, bb0 + 2);
                mma_bf16(C3[0][2], a0, bb1);   mma_bf16(C3[0][3], a0, bb1 + 2);
                mma_bf16(C3[0][4], a0, bb2);
                mma_bf16(C3[1][0], a1, bb0);   mma_bf16(C3[1][1], a1, bb0 + 2);
                mma_bf16(C3[1][2], a1, bb1);   mma_bf16(C3[1][3], a1, bb1 + 2);
                mma_bf16(C3[1][4], a1, bb2);
            }
        }
        __syncthreads();   // (C) strip done; E free
    }

    if (tid < 320) cs[tid] = __fdividef(1.f, cs[tid]);
    __syncthreads();

    {   // out_r = x_r + gamma * (C3 * cinv)
        const float* xr = x_r + cmb;
        float* orr = out_r + cmb;
        int m0 = wy3 * 32, n0 = wx3 * 40;
        #pragma unroll
        for (int mt = 0; mt < 2; mt++) {
            int c0 = m0 + mt*16 + g;
            float g0 = gamma[c0], g1 = gamma[c0 + 8];
            #pragma unroll
            for (int nt = 0; nt < 5; nt++) {
                int col = n0 + nt*8 + 2*t;
                float ci0 = cs[col], ci1 = cs[col + 1];
                float2 x0 = *(const float2*)(xr + (size_t)c0*HWP + col);
                *(float2*)(orr + (size_t)c0*HWP + col) = make_float2(
                    x0.x + g0*ci0*C3[mt][nt][0], x0.y + g0*ci1*C3[mt][nt][1]);
                float2 x1 = *(const float2*)(xr + (size_t)(c0+8)*HWP + col);
                *(float2*)(orr + (size_t)(c0+8)*HWP + col) = make_float2(
                    x1.x + g1*ci0*C3[mt][nt][2], x1.y + g1*ci1*C3[mt][nt][3]);
            }
        }
    }
}

extern "C" void kernel_launch(void* const* d_in, const int* in_sizes, int n_in,
                              void* d_out, int out_size)
{
    const float* x_l    = (const float*)d_in[0];
    const float* x_r    = (const float*)d_in[1];
    const float* ln_l_w = (const float*)d_in[2];
    const float* ln_l_b = (const float*)d_in[3];
    const float* ln_r_w = (const float*)d_in[4];
    const float* ln_r_b = (const float*)d_in[5];
    const float* wq_l   = (const float*)d_in[6];
    const float* bq_l   = (const float*)d_in[7];
    const float* wq_r   = (const float*)d_in[8];
    const float* bq_r   = (const float*)d_in[9];
    const float* wv_l   = (const float*)d_in[10];
    const float* bv_l   = (const float*)d_in[11];
    const float* wv_r   = (const float*)d_in[12];
    const float* bv_r   = (const float*)d_in[13];
    const float* beta   = (const float*)d_in[14];
    const float* gamma  = (const float*)d_in[15];

    float* out_l = (float*)d_out;
    float* out_r = out_l + NELT;

    cudaFuncSetAttribute(sfam_fused_kernel,
                         cudaFuncAttributeMaxDynamicSharedMemorySize, SM_TOTW*4);

    sfam_fused_kernel<<<BB*HH, 512, SM_TOTW*4>>>(
        x_l, x_r, ln_l_w, ln_l_b, ln_r_w, ln_r_b,
        wq_l, bq_l, wq_r, bq_r, wv_l, bv_l, wv_r, bv_r,
        beta, gamma, out_l, out_r);
}